// round 7
// baseline (speedup 1.0000x reference)
#include <cuda_runtime.h>
#include <math.h>

// MonotonicSpline: y[i] = cubic uniform B-spline(clip(x[i],0,1)).
// coef[0]=c0; coef[j]=c0 + sum_{i<j}(MIN+(MAX-MIN)*sigmoid(raw_delta[i])).
// Uniform knots h=1/40 -> per-segment cubic y = ((a*u+b)*u+c)*u+d, u=frac(40x).
// Fused kernel, exact-residency grid (148 SMs x 6 blocks), grid-stride loop
// with DEPTH-2 software pipeline (two LDG.128 in flight per warp) to cover
// ~577-cycle DRAM latency. 8-way bank-replicated smem poly table (LDS.128,
// conflict-free). Streaming cache hints (ldcs/stcs) for the one-touch data.

static constexpr int   NUM_KNOTS  = 40;
static constexpr float MIN_DELTA  = 0.5f / NUM_KNOTS;
static constexpr float MAX_DELTA  = 3.0f / NUM_KNOTS;
static constexpr int   THREADS    = 256;
static constexpr int   BLOCKS_SM  = 6;
static constexpr int   MAX_BLOCKS = 148 * BLOCKS_SM;   // one exact wave at <=42 regs

__device__ __forceinline__ float eval_one(float xv, const float4* __restrict__ rep,
                                          int lane8) {
    float t   = __saturatef(xv) * (float)NUM_KNOTS;   // t in [0,40]
    int   idx = min(__float2int_rz(t), NUM_KNOTS - 1);
    float u   = t - (float)idx;                        // u in [0,1]
    float4 p  = rep[idx * 8 + lane8];                  // conflict-free LDS.128
    return ((p.w * u + p.z) * u + p.y) * u + p.x;
}

__global__ void __launch_bounds__(THREADS, BLOCKS_SM)
spline_fused_kernel(const float* __restrict__ x,
                    const float* __restrict__ c0,
                    const float* __restrict__ raw_delta,
                    float* __restrict__ y,
                    int n4, int n) {
    __shared__ float  coef[NUM_KNOTS + 3];      // 43
    __shared__ float4 rep[NUM_KNOTS * 8];       // 8-way replicated table, 5 KB

    const int tid    = threadIdx.x;
    const int lane   = tid & 31;
    const int stride = gridDim.x * THREADS;
    const float4* __restrict__ x4 = reinterpret_cast<const float4*>(x);
    float4* __restrict__ y4 = reinterpret_cast<float4*>(y);

    // ---- prime a depth-2 pipeline BEFORE the table prologue ----
    int  i  = blockIdx.x * THREADS + tid;
    bool h0 = (i < n4);
    bool h1 = (i + stride < n4);
    float4 v0, v1;
    if (h0) v0 = __ldcs(&x4[i]);
    if (h1) v1 = __ldcs(&x4[i + stride]);

    // ---- warp 0: sigmoid deltas -> scan -> coef -> replicated poly table ----
    if (tid < 32) {
        const float scale = MAX_DELTA - MIN_DELTA;
        float d0 = MIN_DELTA + scale / (1.0f + __expf(-raw_delta[lane]));
        float d1 = 0.0f;
        if (lane < 10)
            d1 = MIN_DELTA + scale / (1.0f + __expf(-raw_delta[lane + 32]));
        #pragma unroll
        for (int off = 1; off < 32; off <<= 1) {
            float t0 = __shfl_up_sync(0xffffffffu, d0, off);
            float t1 = __shfl_up_sync(0xffffffffu, d1, off);
            if (lane >= off) { d0 += t0; d1 += t1; }
        }
        float tot0 = __shfl_sync(0xffffffffu, d0, 31);
        float c0v  = __ldg(c0);
        if (lane == 0) coef[0] = c0v;
        coef[lane + 1] = c0v + d0;                        // coef[1..32]
        if (lane < 10) coef[lane + 33] = c0v + tot0 + d1; // coef[33..42]
        __syncwarp();
        #pragma unroll
        for (int e = lane; e < NUM_KNOTS * 8; e += 32) {  // conflict-free STS.128
            int j = e >> 3;
            float p0 = coef[j], p1 = coef[j + 1], p2 = coef[j + 2], p3 = coef[j + 3];
            float4 o;
            o.x = (p0 + 4.0f * p1 + p2) * (1.0f / 6.0f);
            o.y = (p2 - p0) * 0.5f;
            o.z = (p0 - 2.0f * p1 + p2) * 0.5f;
            o.w = (p3 - p0 + 3.0f * (p1 - p2)) * (1.0f / 6.0f);
            rep[e] = o;
        }
    }
    __syncthreads();

    // ---- grid-stride depth-2 pipelined loop ----
    // unroll 1: unrolling would merge iterations and collapse the prefetch
    // distance (registers ballooned to 57 when this happened in round 3).
    const int lane8 = tid & 7;
    #pragma unroll 1
    while (h0) {
        int  i2 = i + 2 * stride;
        bool h2 = (i2 < n4);
        float4 v2;
        if (h2) v2 = __ldcs(&x4[i2]);      // 2 loads in flight during compute

        float4 o;
        o.x = eval_one(v0.x, rep, lane8);
        o.y = eval_one(v0.y, rep, lane8);
        o.z = eval_one(v0.z, rep, lane8);
        o.w = eval_one(v0.w, rep, lane8);
        __stcs(&y4[i], o);

        v0 = v1; h0 = h1;
        v1 = v2; h1 = h2;
        i += stride;
    }

    // scalar tail (n % 4 != 0) — block 0 only
    if (blockIdx.x == 0) {
        int j = n4 * 4 + tid;
        if (j < n) y[j] = eval_one(x[j], rep, lane8);
    }
}

extern "C" void kernel_launch(void* const* d_in, const int* in_sizes, int n_in,
                              void* d_out, int out_size) {
    const float* x         = (const float*)d_in[0];
    // d_in[1] = grid (uniform; values implied by construction)
    const float* c0        = (const float*)d_in[2];
    const float* raw_delta = (const float*)d_in[3];
    float* y = (float*)d_out;

    int n  = in_sizes[0];
    int n4 = n / 4;

    int blocks = (n4 + THREADS - 1) / THREADS;
    if (blocks > MAX_BLOCKS) blocks = MAX_BLOCKS;
    if (blocks == 0) blocks = 1;

    spline_fused_kernel<<<blocks, THREADS>>>(x, c0, raw_delta, y, n4, n);
}